// round 5
// baseline (speedup 1.0000x reference)
#include <cuda_runtime.h>
#include <cuda_bf16.h>
#include <math.h>

// Problem constants
#define BB 4
#define SS 1024
#define KK 32
#define VV 32000
#define ROWS (BB * SS)        // 4096
#define FULL 0xFFFFFFFFu

#define SCATTER_THREADS 256
#define ROWS_PER_BLOCK (SCATTER_THREADS / 32)   // 8 rows (one per warp)

// Per-row math + scatter: one warp per row. Output must already be zeroed.
__global__ __launch_bounds__(SCATTER_THREADS)
void robust_scatter_kernel(
    const int*   __restrict__ tgt_index,            // [ROWS, 32]
    const float* __restrict__ knn_dists,            // [ROWS, 32]
    const float* __restrict__ knn_key_feature,      // [ROWS, 32]
    const float* __restrict__ network_select_probs, // [ROWS, 32]
    const float* __restrict__ fc1_w1,               // [2,4]
    const float* __restrict__ fc1_b1,               // [4]
    const float* __restrict__ fc1_w2,               // [4,1]
    const float* __restrict__ fc1_b2,               // [1]
    const float* __restrict__ fc2_w1,               // [64,32]
    const float* __restrict__ fc2_b1,               // [32]
    const float* __restrict__ fc2_w2,               // [32,2]
    const float* __restrict__ fc2_b2,               // [2]
    float*       __restrict__ out)                  // [ROWS, 32000]
{
    const int tid  = threadIdx.x;
    const int lane = tid & 31;
    const int row  = blockIdx.x * ROWS_PER_BLOCK + (tid >> 5);

    const int base = row * KK + lane;
    const int   t  = tgt_index[base];
    const float d  = knn_dists[base];
    const float lkf = logf(knn_key_feature[base]);
    const float lsp = logf(network_select_probs[base]);

    // ---- label_counts: distinct nonzero labels in prefix [0..lane] ----
    int dup = 0;
    #pragma unroll
    for (int m = 0; m < KK; m++) {
        int tm = __shfl_sync(FULL, t, m);
        if (m < lane && tm == t) dup = 1;
    }
    int c = (t != 0 && !dup) ? 1 : 0;
    #pragma unroll
    for (int off = 1; off < 32; off <<= 1) {
        int v = __shfl_up_sync(FULL, c, off);
        if (lane >= off) c += v;
    }
    const float lc = (float)c;

    // ---- noise_logit: Linear(2,4) -> tanh -> Linear(4,1) ----
    float noise = fc1_b2[0];
    #pragma unroll
    for (int j = 0; j < 4; j++) {
        float h = tanhf(lkf * fc1_w1[j] + lsp * fc1_w1[4 + j] + fc1_b1[j]);
        noise += h * fc1_w2[j];
    }

    // ---- fc2: Linear(64,32)->tanh->Linear(32,2)[1]; lane = hidden unit ----
    float acc = fc2_b1[lane];
    #pragma unroll
    for (int m = 0; m < KK; m++) {
        float dm = __shfl_sync(FULL, d, m);
        acc = fmaf(dm, fc2_w1[m * 32 + lane], acc);
    }
    #pragma unroll
    for (int m = 0; m < KK; m++) {
        float lcm = __shfl_sync(FULL, lc, m);
        acc = fmaf(lcm, fc2_w1[(KK + m) * 32 + lane], acc);
    }
    float h = tanhf(acc);

    // lambda_logit[1] warp-reduce
    float part = h * fc2_w2[lane * 2 + 1];
    #pragma unroll
    for (int off = 16; off >= 1; off >>= 1)
        part += __shfl_xor_sync(FULL, part, off);
    const float tempe = 1.0f / (1.0f + expf(-(part + fc2_b2[1])));

    // ---- probs = softmax(-d * tempe + noise) over K ----
    float logit = fmaf(-d, tempe, noise);
    float mx = logit;
    #pragma unroll
    for (int off = 16; off >= 1; off >>= 1)
        mx = fmaxf(mx, __shfl_xor_sync(FULL, mx, off));
    float e = expf(logit - mx);
    float s = e;
    #pragma unroll
    for (int off = 16; off >= 1; off >>= 1)
        s += __shfl_xor_sync(FULL, s, off);

    const float prob = e / s;

    // ---- scatter_add (atomic handles intra-row duplicate indices) ----
    atomicAdd(out + (size_t)row * VV + t, prob);
}

extern "C" void kernel_launch(void* const* d_in, const int* in_sizes, int n_in,
                              void* d_out, int out_size)
{
    // metadata order (setup_inputs order):
    // 0 tgt_index i32, 1 knn_dists f32, 2 knn_key_feature f32,
    // 3 network_probs f32 (UNUSED — dead code in reference),
    // 4 network_select_probs f32, 5 dfc_w (UNUSED), 6 dfc_b (UNUSED),
    // 7 fc1_w1, 8 fc1_b1, 9 fc1_w2, 10 fc1_b2,
    // 11 fc2_w1, 12 fc2_b1, 13 fc2_w2, 14 fc2_b2
    const int*   tgt  = (const int*)  d_in[0];
    const float* kd   = (const float*)d_in[1];
    const float* kkf  = (const float*)d_in[2];
    const float* nsp  = (const float*)d_in[4];
    const float* f1w1 = (const float*)d_in[7];
    const float* f1b1 = (const float*)d_in[8];
    const float* f1w2 = (const float*)d_in[9];
    const float* f1b2 = (const float*)d_in[10];
    const float* f2w1 = (const float*)d_in[11];
    const float* f2b1 = (const float*)d_in[12];
    const float* f2w2 = (const float*)d_in[13];
    const float* f2b2 = (const float*)d_in[14];
    float* out = (float*)d_out;

    // 1) Bulk zero of the output via the driver's tuned fill path
    //    (memset node in the captured graph; no allocation, no sync).
    cudaMemsetAsync(out, 0, (size_t)ROWS * VV * sizeof(float), 0);

    // 2) Tiny per-row math + scatter-add kernel (one warp per row).
    robust_scatter_kernel<<<ROWS / ROWS_PER_BLOCK, SCATTER_THREADS>>>(
        tgt, kd, kkf, nsp,
        f1w1, f1b1, f1w2, f1b2,
        f2w1, f2b1, f2w2, f2b2,
        out);
}